// round 2
// baseline (speedup 1.0000x reference)
#include <cuda_runtime.h>
#include <math.h>
#include <float.h>

#define N_NODES 81920
#define N_SESS 4096
#define NPS 20
#define N_EDGES 163840
#define IN_DIM 771
#define INIT_DIM 128
#define HID 100
#define N_ITEMS 50000

// ---------------- scratch (device globals; no allocation allowed) ----------------
__device__ float g_feat[(size_t)N_NODES * IN_DIM];     // 252.6 MB
__device__ float g_proj[(size_t)N_NODES * INIT_DIM];   // 42 MB
__device__ float g_h[(size_t)N_NODES * HID];           // 32.8 MB
__device__ float g_msum[(size_t)N_NODES * HID];        // 32.8 MB
__device__ float g_cnt[N_NODES];
__device__ float g_m[(size_t)N_NODES * HID];           // 32.8 MB
__device__ float g_gi[(size_t)N_NODES * 3 * HID];      // 98 MB  (reused as tmp for gate layer1)
__device__ float g_gh[(size_t)N_NODES * 3 * HID];      // 98 MB
__device__ float g_featlast[(size_t)N_SESS * IN_DIM];  // 12.6 MB
__device__ float g_last[(size_t)N_SESS * HID];
__device__ float g_gate[N_NODES];
__device__ float g_pooled[(size_t)N_SESS * HID];

// ---------------- elementwise / glue kernels ----------------

__global__ void __launch_bounds__(256) concat_feat_kernel(
        const float* __restrict__ cat,
        const float* __restrict__ sub,
        const float* __restrict__ elem,
        const float* __restrict__ brand,
        const float* __restrict__ price) {
    size_t idx = (size_t)blockIdx.x * blockDim.x + threadIdx.x;
    if (idx >= (size_t)N_NODES * IN_DIM) return;
    int n = (int)(idx / IN_DIM);
    int c = (int)(idx % IN_DIM);
    float v;
    if (c < 20)        v = cat[n * 20 + c];
    else if (c < 170)  v = sub[n * 150 + (c - 20)];
    else if (c < 270)  v = elem[n * 100 + (c - 170)];
    else if (c < 770)  v = brand[n * 500 + (c - 270)];
    else               v = price[n];
    g_feat[idx] = v;
}

__global__ void __launch_bounds__(256) zero_msum_cnt_kernel() {
    size_t idx = (size_t)blockIdx.x * blockDim.x + threadIdx.x;
    if (idx < (size_t)N_NODES * HID) g_msum[idx] = 0.0f;
    if (idx < N_NODES) g_cnt[idx] = 0.0f;
}

// 2 edges per 256-thread block: threads [0,128) -> edge 2b, [128,256) -> edge 2b+1
__global__ void __launch_bounds__(256) edge_scatter_kernel(const int* __restrict__ ei) {
    int e = blockIdx.x * 2 + (threadIdx.x >> 7);
    if (e >= N_EDGES) return;
    int j = threadIdx.x & 127;
    int src = ei[e];
    int dst = ei[N_EDGES + e];
    if (j < HID) {
        atomicAdd(&g_msum[(size_t)dst * HID + j], g_h[(size_t)src * HID + j]);
    } else if (j == HID) {
        atomicAdd(&g_cnt[dst], 1.0f);
    }
}

__global__ void __launch_bounds__(256) mean_kernel() {
    size_t idx = (size_t)blockIdx.x * blockDim.x + threadIdx.x;
    if (idx >= (size_t)N_NODES * HID) return;
    int n = (int)(idx / HID);
    g_m[idx] = g_msum[idx] / fmaxf(g_cnt[n], 1.0f);
}

__device__ __forceinline__ float sigmoidf(float x) { return 1.0f / (1.0f + expf(-x)); }

__global__ void __launch_bounds__(256) gru_kernel() {
    size_t idx = (size_t)blockIdx.x * blockDim.x + threadIdx.x;
    if (idx >= (size_t)N_NODES * HID) return;
    int n = (int)(idx / HID);
    int j = (int)(idx % HID);
    size_t base = (size_t)n * 3 * HID;
    float gir = g_gi[base + j],         ghr = g_gh[base + j];
    float giz = g_gi[base + HID + j],   ghz = g_gh[base + HID + j];
    float gin = g_gi[base + 2*HID + j], ghn = g_gh[base + 2*HID + j];
    float r = sigmoidf(gir + ghr);
    float z = sigmoidf(giz + ghz);
    float nn = tanhf(gin + r * ghn);
    float hold = g_h[idx];
    g_h[idx] = (1.0f - z) * nn + z * hold;
}

__global__ void __launch_bounds__(256) gather_last_kernel() {
    size_t idx = (size_t)blockIdx.x * blockDim.x + threadIdx.x;
    if (idx >= (size_t)N_SESS * IN_DIM) return;
    int s = (int)(idx / IN_DIM);
    int c = (int)(idx % IN_DIM);
    g_featlast[idx] = g_feat[(size_t)(s * NPS + NPS - 1) * IN_DIM + c];
}

__global__ void __launch_bounds__(256) add_last_kernel(const int* __restrict__ batch) {
    size_t idx = (size_t)blockIdx.x * blockDim.x + threadIdx.x;
    if (idx >= (size_t)N_NODES * HID) return;
    int n = (int)(idx / HID);
    int j = (int)(idx % HID);
    g_h[idx] += g_last[(size_t)batch[n] * HID + j];
}

// gate[n] = tmp(row n) . W_g2 + b_g2  (tmp = relu layer stored in g_gi)
__global__ void __launch_bounds__(256) gate_dot_kernel(
        const float* __restrict__ Wg2, const float* __restrict__ bg2) {
    int warp = (blockIdx.x * blockDim.x + threadIdx.x) >> 5;
    int lane = threadIdx.x & 31;
    if (warp >= N_NODES) return;
    float acc = 0.0f;
    for (int k = lane; k < HID; k += 32)
        acc += g_gi[(size_t)warp * HID + k] * Wg2[k];
    #pragma unroll
    for (int off = 16; off > 0; off >>= 1)
        acc += __shfl_xor_sync(0xffffffffu, acc, off);
    if (lane == 0) g_gate[warp] = acc + bg2[0];
}

// per-session softmax over 20 contiguous nodes + weighted pooling
__global__ void __launch_bounds__(128) pool_kernel() {
    int s = blockIdx.x;
    int t = threadIdx.x;  // 128 threads
    __shared__ float e[NPS];
    __shared__ float s_den;
    if (t < 32) {
        float g = (t < NPS) ? g_gate[s * NPS + t] : -FLT_MAX;
        float mx = g;
        #pragma unroll
        for (int off = 16; off > 0; off >>= 1)
            mx = fmaxf(mx, __shfl_xor_sync(0xffffffffu, mx, off));
        float ex = (t < NPS) ? expf(g - mx) : 0.0f;
        float sum = ex;
        #pragma unroll
        for (int off = 16; off > 0; off >>= 1)
            sum += __shfl_xor_sync(0xffffffffu, sum, off);
        if (t < NPS) e[t] = ex;
        if (t == 0) s_den = sum;
    }
    __syncthreads();
    if (t < HID) {
        float inv = 1.0f / s_den;
        float acc = 0.0f;
        #pragma unroll
        for (int i = 0; i < NPS; i++)
            acc += e[i] * g_h[(size_t)(s * NPS + i) * HID + t];
        g_pooled[(size_t)s * HID + t] = acc * inv;
    }
}

// ---------------- generic tiled SGEMM: C[M,N] = A[M,K] @ B[N,K]^T + bias, opt relu ----------------
__global__ void __launch_bounds__(256) sgemm_nt_kernel(
    const float* __restrict__ A, const float* __restrict__ B,
    const float* __restrict__ bias, float* __restrict__ C,
    int M, int N, int K, int do_relu)
{
    const int BM = 64, BN = 64, BK = 16;
    __shared__ float As[BK][BM + 1];
    __shared__ float Bs[BK][BN + 1];

    int bm = blockIdx.y * BM;
    int bn = blockIdx.x * BN;
    int tx = threadIdx.x & 15;   // 0..15 -> N direction
    int ty = threadIdx.x >> 4;   // 0..15 -> M direction

    float acc[4][4];
    #pragma unroll
    for (int i = 0; i < 4; i++)
        #pragma unroll
        for (int j = 0; j < 4; j++) acc[i][j] = 0.0f;

    for (int k0 = 0; k0 < K; k0 += BK) {
        #pragma unroll 4
        for (int i = threadIdx.x; i < BM * BK; i += 256) {
            int m = i >> 4, k = i & 15;
            float v = 0.0f;
            if (bm + m < M && k0 + k < K)
                v = A[(size_t)(bm + m) * K + k0 + k];
            As[k][m] = v;
        }
        #pragma unroll 4
        for (int i = threadIdx.x; i < BN * BK; i += 256) {
            int n = i >> 4, k = i & 15;
            float v = 0.0f;
            if (bn + n < N && k0 + k < K)
                v = B[(size_t)(bn + n) * K + k0 + k];
            Bs[k][n] = v;
        }
        __syncthreads();
        #pragma unroll
        for (int kk = 0; kk < BK; kk++) {
            float a[4], b[4];
            #pragma unroll
            for (int i = 0; i < 4; i++) a[i] = As[kk][ty * 4 + i];
            #pragma unroll
            for (int j = 0; j < 4; j++) b[j] = Bs[kk][tx * 4 + j];
            #pragma unroll
            for (int i = 0; i < 4; i++)
                #pragma unroll
                for (int j = 0; j < 4; j++)
                    acc[i][j] += a[i] * b[j];
        }
        __syncthreads();
    }

    #pragma unroll
    for (int i = 0; i < 4; i++) {
        int m = bm + ty * 4 + i;
        if (m >= M) continue;
        #pragma unroll
        for (int j = 0; j < 4; j++) {
            int n = bn + tx * 4 + j;
            if (n >= N) continue;
            float v = acc[i][j] + bias[n];
            if (do_relu) v = fmaxf(v, 0.0f);
            C[(size_t)m * N + n] = v;
        }
    }
}

// ---------------- launch ----------------

static inline dim3 gemm_grid(int M, int N) {
    return dim3((N + 63) / 64, (M + 63) / 64);
}

extern "C" void kernel_launch(void* const* d_in, const int* in_sizes, int n_in,
                              void* d_out, int out_size) {
    const float* category  = (const float*)d_in[0];
    const float* sub_cat   = (const float*)d_in[1];
    const float* element   = (const float*)d_in[2];
    const float* brand     = (const float*)d_in[3];
    const float* price     = (const float*)d_in[4];
    const int*   edge_idx  = (const int*)d_in[5];
    const int*   batch     = (const int*)d_in[6];
    const float* W_init = (const float*)d_in[7];
    const float* b_init = (const float*)d_in[8];
    const float* W_msg  = (const float*)d_in[9];
    const float* b_msg  = (const float*)d_in[10];
    const float* W_ih   = (const float*)d_in[11];
    const float* W_hh   = (const float*)d_in[12];
    const float* b_ih   = (const float*)d_in[13];
    const float* b_hh   = (const float*)d_in[14];
    const float* W_last = (const float*)d_in[15];
    const float* b_last = (const float*)d_in[16];
    const float* W_g1   = (const float*)d_in[17];
    const float* b_g1   = (const float*)d_in[18];
    const float* W_g2   = (const float*)d_in[19];
    const float* b_g2   = (const float*)d_in[20];
    const float* W_fc   = (const float*)d_in[21];
    const float* b_fc   = (const float*)d_in[22];
    float* out = (float*)d_out;

    float *feat, *proj, *h, *m, *gi, *gh, *featlast, *last, *pooled;
    cudaGetSymbolAddress((void**)&feat, g_feat);
    cudaGetSymbolAddress((void**)&proj, g_proj);
    cudaGetSymbolAddress((void**)&h, g_h);
    cudaGetSymbolAddress((void**)&m, g_m);
    cudaGetSymbolAddress((void**)&gi, g_gi);
    cudaGetSymbolAddress((void**)&gh, g_gh);
    cudaGetSymbolAddress((void**)&featlast, g_featlast);
    cudaGetSymbolAddress((void**)&last, g_last);
    cudaGetSymbolAddress((void**)&pooled, g_pooled);

    const size_t NF = (size_t)N_NODES * IN_DIM;
    const size_t NH = (size_t)N_NODES * HID;

    // 1) feat concat
    concat_feat_kernel<<<(unsigned)((NF + 255) / 256), 256>>>(category, sub_cat, element, brand, price);

    // 2) proj = feat @ W_init^T + b_init   [81920,128]
    sgemm_nt_kernel<<<gemm_grid(N_NODES, INIT_DIM), 256>>>(feat, W_init, b_init, proj, N_NODES, INIT_DIM, IN_DIM, 0);

    // 3) h = proj @ W_msg^T + b_msg        [81920,100]
    sgemm_nt_kernel<<<gemm_grid(N_NODES, HID), 256>>>(proj, W_msg, b_msg, h, N_NODES, HID, INIT_DIM, 0);

    // 4) message passing mean
    zero_msum_cnt_kernel<<<(unsigned)((NH + 255) / 256), 256>>>();
    edge_scatter_kernel<<<(N_EDGES + 1) / 2, 256>>>(edge_idx);
    mean_kernel<<<(unsigned)((NH + 255) / 256), 256>>>();

    // 5) GRU
    sgemm_nt_kernel<<<gemm_grid(N_NODES, 3 * HID), 256>>>(m, W_ih, b_ih, gi, N_NODES, 3 * HID, HID, 0);
    sgemm_nt_kernel<<<gemm_grid(N_NODES, 3 * HID), 256>>>(h, W_hh, b_hh, gh, N_NODES, 3 * HID, HID, 0);
    gru_kernel<<<(unsigned)((NH + 255) / 256), 256>>>();

    // 6) last-node projection, broadcast add
    gather_last_kernel<<<(unsigned)(((size_t)N_SESS * IN_DIM + 255) / 256), 256>>>();
    sgemm_nt_kernel<<<gemm_grid(N_SESS, HID), 256>>>(featlast, W_last, b_last, last, N_SESS, HID, IN_DIM, 0);
    add_last_kernel<<<(unsigned)((NH + 255) / 256), 256>>>(batch);

    // 7) attention gate: tmp = relu(h@Wg1^T + bg1) in g_gi; gate = tmp@Wg2^T + bg2
    sgemm_nt_kernel<<<gemm_grid(N_NODES, HID), 256>>>(h, W_g1, b_g1, gi, N_NODES, HID, HID, 1);
    gate_dot_kernel<<<(N_NODES * 32 + 255) / 256, 256>>>(W_g2, b_g2);

    // 8) per-session softmax + pooling
    pool_kernel<<<N_SESS, 128>>>();

    // 9) out = pooled @ W_fc^T + b_fc   [4096, 50000]
    sgemm_nt_kernel<<<gemm_grid(N_SESS, N_ITEMS), 256>>>(pooled, W_fc, b_fc, out, N_SESS, N_ITEMS, HID, 0);
}

// round 5
// speedup vs baseline: 2.0716x; 2.0716x over previous
#include <cuda_runtime.h>
#include <math.h>
#include <float.h>
#include <stdint.h>

#define N_NODES 81920
#define N_SESS 4096
#define NPS 20
#define N_EDGES 163840
#define IN_DIM 771
#define INIT_DIM 128
#define HID 100
#define N_ITEMS 50000

// ---------------- scratch (device globals; no allocation allowed) ----------------
__device__ float g_feat[(size_t)N_NODES * IN_DIM];     // 252.6 MB
__device__ float g_proj[(size_t)N_NODES * INIT_DIM];   // 42 MB
__device__ float g_h[(size_t)N_NODES * HID];           // 32.8 MB
__device__ float g_msum[(size_t)N_NODES * HID];        // 32.8 MB
__device__ float g_cnt[N_NODES];
__device__ float g_m[(size_t)N_NODES * HID];           // 32.8 MB
__device__ float g_gi[(size_t)N_NODES * 3 * HID];      // 98 MB  (reused as tmp for gate layer1)
__device__ float g_gh[(size_t)N_NODES * 3 * HID];      // 98 MB
__device__ float g_featlast[(size_t)N_SESS * IN_DIM];  // 12.6 MB
__device__ float g_last[(size_t)N_SESS * HID];
__device__ float g_gate[N_NODES];
__device__ float g_pooled[(size_t)N_SESS * HID];

// ---------------- elementwise / glue kernels ----------------

__global__ void __launch_bounds__(256) concat_feat_kernel(
        const float* __restrict__ cat,
        const float* __restrict__ sub,
        const float* __restrict__ elem,
        const float* __restrict__ brand,
        const float* __restrict__ price) {
    size_t idx = (size_t)blockIdx.x * blockDim.x + threadIdx.x;
    if (idx >= (size_t)N_NODES * IN_DIM) return;
    int n = (int)(idx / IN_DIM);
    int c = (int)(idx % IN_DIM);
    float v;
    if (c < 20)        v = cat[n * 20 + c];
    else if (c < 170)  v = sub[n * 150 + (c - 20)];
    else if (c < 270)  v = elem[n * 100 + (c - 170)];
    else if (c < 770)  v = brand[n * 500 + (c - 270)];
    else               v = price[n];
    g_feat[idx] = v;
}

__global__ void __launch_bounds__(256) zero_msum_cnt_kernel() {
    size_t idx = (size_t)blockIdx.x * blockDim.x + threadIdx.x;
    if (idx < (size_t)N_NODES * HID) g_msum[idx] = 0.0f;
    if (idx < N_NODES) g_cnt[idx] = 0.0f;
}

// 2 edges per 256-thread block
__global__ void __launch_bounds__(256) edge_scatter_kernel(const int* __restrict__ ei) {
    int e = blockIdx.x * 2 + (threadIdx.x >> 7);
    if (e >= N_EDGES) return;
    int j = threadIdx.x & 127;
    int src = ei[e];
    int dst = ei[N_EDGES + e];
    if (j < HID) {
        atomicAdd(&g_msum[(size_t)dst * HID + j], g_h[(size_t)src * HID + j]);
    } else if (j == HID) {
        atomicAdd(&g_cnt[dst], 1.0f);
    }
}

__global__ void __launch_bounds__(256) mean_kernel() {
    size_t idx = (size_t)blockIdx.x * blockDim.x + threadIdx.x;
    if (idx >= (size_t)N_NODES * HID) return;
    int n = (int)(idx / HID);
    g_m[idx] = g_msum[idx] / fmaxf(g_cnt[n], 1.0f);
}

__device__ __forceinline__ float sigmoidf(float x) { return 1.0f / (1.0f + expf(-x)); }

__global__ void __launch_bounds__(256) gru_kernel() {
    size_t idx = (size_t)blockIdx.x * blockDim.x + threadIdx.x;
    if (idx >= (size_t)N_NODES * HID) return;
    int n = (int)(idx / HID);
    int j = (int)(idx % HID);
    size_t base = (size_t)n * 3 * HID;
    float gir = g_gi[base + j],         ghr = g_gh[base + j];
    float giz = g_gi[base + HID + j],   ghz = g_gh[base + HID + j];
    float gin = g_gi[base + 2*HID + j], ghn = g_gh[base + 2*HID + j];
    float r = sigmoidf(gir + ghr);
    float z = sigmoidf(giz + ghz);
    float nn = tanhf(gin + r * ghn);
    float hold = g_h[idx];
    g_h[idx] = (1.0f - z) * nn + z * hold;
}

__global__ void __launch_bounds__(256) gather_last_kernel() {
    size_t idx = (size_t)blockIdx.x * blockDim.x + threadIdx.x;
    if (idx >= (size_t)N_SESS * IN_DIM) return;
    int s = (int)(idx / IN_DIM);
    int c = (int)(idx % IN_DIM);
    g_featlast[idx] = g_feat[(size_t)(s * NPS + NPS - 1) * IN_DIM + c];
}

__global__ void __launch_bounds__(256) add_last_kernel(const int* __restrict__ batch) {
    size_t idx = (size_t)blockIdx.x * blockDim.x + threadIdx.x;
    if (idx >= (size_t)N_NODES * HID) return;
    int n = (int)(idx / HID);
    int j = (int)(idx % HID);
    g_h[idx] += g_last[(size_t)batch[n] * HID + j];
}

// gate[n] = tmp(row n) . W_g2 + b_g2  (tmp = relu layer stored in g_gi)
__global__ void __launch_bounds__(256) gate_dot_kernel(
        const float* __restrict__ Wg2, const float* __restrict__ bg2) {
    int warp = (blockIdx.x * blockDim.x + threadIdx.x) >> 5;
    int lane = threadIdx.x & 31;
    if (warp >= N_NODES) return;
    float acc = 0.0f;
    for (int k = lane; k < HID; k += 32)
        acc += g_gi[(size_t)warp * HID + k] * Wg2[k];
    #pragma unroll
    for (int off = 16; off > 0; off >>= 1)
        acc += __shfl_xor_sync(0xffffffffu, acc, off);
    if (lane == 0) g_gate[warp] = acc + bg2[0];
}

// per-session softmax over 20 contiguous nodes + weighted pooling
__global__ void __launch_bounds__(128) pool_kernel() {
    int s = blockIdx.x;
    int t = threadIdx.x;  // 128 threads
    __shared__ float e[NPS];
    __shared__ float s_den;
    if (t < 32) {
        float g = (t < NPS) ? g_gate[s * NPS + t] : -FLT_MAX;
        float mx = g;
        #pragma unroll
        for (int off = 16; off > 0; off >>= 1)
            mx = fmaxf(mx, __shfl_xor_sync(0xffffffffu, mx, off));
        float ex = (t < NPS) ? expf(g - mx) : 0.0f;
        float sum = ex;
        #pragma unroll
        for (int off = 16; off > 0; off >>= 1)
            sum += __shfl_xor_sync(0xffffffffu, sum, off);
        if (t < NPS) e[t] = ex;
        if (t == 0) s_den = sum;
    }
    __syncthreads();
    if (t < HID) {
        float inv = 1.0f / s_den;
        float acc = 0.0f;
        #pragma unroll
        for (int i = 0; i < NPS; i++)
            acc += e[i] * g_h[(size_t)(s * NPS + i) * HID + t];
        g_pooled[(size_t)s * HID + t] = acc * inv;
    }
}

// ---------------- fp32 fallback SGEMM (small GEMMs, keeps error chain short) ----------------
__global__ void __launch_bounds__(256) sgemm_nt_kernel(
    const float* __restrict__ A, const float* __restrict__ B,
    const float* __restrict__ bias, float* __restrict__ C,
    int M, int N, int K, int do_relu)
{
    const int BM = 64, BN = 64, BK = 16;
    __shared__ float As[BK][BM + 1];
    __shared__ float Bs[BK][BN + 1];

    int bm = blockIdx.y * BM;
    int bn = blockIdx.x * BN;
    int tx = threadIdx.x & 15;
    int ty = threadIdx.x >> 4;

    float acc[4][4];
    #pragma unroll
    for (int i = 0; i < 4; i++)
        #pragma unroll
        for (int j = 0; j < 4; j++) acc[i][j] = 0.0f;

    for (int k0 = 0; k0 < K; k0 += BK) {
        #pragma unroll 4
        for (int i = threadIdx.x; i < BM * BK; i += 256) {
            int m = i >> 4, k = i & 15;
            float v = 0.0f;
            if (bm + m < M && k0 + k < K)
                v = A[(size_t)(bm + m) * K + k0 + k];
            As[k][m] = v;
        }
        #pragma unroll 4
        for (int i = threadIdx.x; i < BN * BK; i += 256) {
            int n = i >> 4, k = i & 15;
            float v = 0.0f;
            if (bn + n < N && k0 + k < K)
                v = B[(size_t)(bn + n) * K + k0 + k];
            Bs[k][n] = v;
        }
        __syncthreads();
        #pragma unroll
        for (int kk = 0; kk < BK; kk++) {
            float a[4], b[4];
            #pragma unroll
            for (int i = 0; i < 4; i++) a[i] = As[kk][ty * 4 + i];
            #pragma unroll
            for (int j = 0; j < 4; j++) b[j] = Bs[kk][tx * 4 + j];
            #pragma unroll
            for (int i = 0; i < 4; i++)
                #pragma unroll
                for (int j = 0; j < 4; j++)
                    acc[i][j] += a[i] * b[j];
        }
        __syncthreads();
    }

    #pragma unroll
    for (int i = 0; i < 4; i++) {
        int m = bm + ty * 4 + i;
        if (m >= M) continue;
        #pragma unroll
        for (int j = 0; j < 4; j++) {
            int n = bn + tx * 4 + j;
            if (n >= N) continue;
            float v = acc[i][j] + bias[n];
            if (do_relu) v = fmaxf(v, 0.0f);
            C[(size_t)m * N + n] = v;
        }
    }
}

// ---------------- TF32 tensor-core GEMM: C[M,N] = A[M,K]@B[N,K]^T + bias, opt relu ----------------
// BM=128, BN=64, BK=32. 256 threads = 8 warps, 4 (M) x 2 (N).
// Warp tile 32x32 = 2 (m16) x 4 (n8) mma tiles. mma.sync.m16n8k8.tf32.
__device__ __forceinline__ float to_tf32(float x) {
    uint32_t u;
    asm("cvt.rna.tf32.f32 %0, %1;" : "=r"(u) : "f"(x));
    return __uint_as_float(u);
}

__global__ void __launch_bounds__(256) tgemm_nt_kernel(
    const float* __restrict__ A, const float* __restrict__ B,
    const float* __restrict__ bias, float* __restrict__ C,
    int M, int N, int K, int do_relu)
{
    const int BM = 128, BN = 64, BK = 32;
    const int LD = BK + 4;                 // 36 floats: bank = (4g+tig) mod 32 -> conflict-free
    __shared__ float As[BM * LD];          // 18.4 KB
    __shared__ float Bs[BN * LD];          // 9.2 KB

    int bm = blockIdx.y * BM;
    int bn = blockIdx.x * BN;
    int tid = threadIdx.x;
    int warp = tid >> 5;
    int lane = tid & 31;
    int g   = lane >> 2;                   // groupID 0..7
    int tig = lane & 3;                    // thread-in-group 0..3
    int mBase = (warp & 3) * 32;           // warp row offset
    int nBase = (warp >> 2) * 32;          // warp col offset

    float acc[2][4][4];
    #pragma unroll
    for (int mi = 0; mi < 2; mi++)
        #pragma unroll
        for (int ni = 0; ni < 4; ni++)
            #pragma unroll
            for (int r = 0; r < 4; r++) acc[mi][ni][r] = 0.0f;

    for (int k0 = 0; k0 < K; k0 += BK) {
        // load A tile (128x32) -- coalesced along K, convert to tf32 once
        #pragma unroll 4
        for (int i = tid; i < BM * BK; i += 256) {
            int m = i >> 5, k = i & 31;
            float v = 0.0f;
            if (bm + m < M && k0 + k < K) v = A[(size_t)(bm + m) * K + k0 + k];
            As[m * LD + k] = to_tf32(v);
        }
        // load B tile (64x32)
        #pragma unroll 4
        for (int i = tid; i < BN * BK; i += 256) {
            int n = i >> 5, k = i & 31;
            float v = 0.0f;
            if (bn + n < N && k0 + k < K) v = B[(size_t)(bn + n) * K + k0 + k];
            Bs[n * LD + k] = to_tf32(v);
        }
        __syncthreads();

        #pragma unroll
        for (int kk = 0; kk < BK; kk += 8) {
            uint32_t afrag[2][4], bfrag[4][2];
            #pragma unroll
            for (int mi = 0; mi < 2; mi++) {
                int r0 = mBase + mi * 16 + g;
                afrag[mi][0] = __float_as_uint(As[r0 * LD + kk + tig]);
                afrag[mi][1] = __float_as_uint(As[(r0 + 8) * LD + kk + tig]);
                afrag[mi][2] = __float_as_uint(As[r0 * LD + kk + tig + 4]);
                afrag[mi][3] = __float_as_uint(As[(r0 + 8) * LD + kk + tig + 4]);
            }
            #pragma unroll
            for (int ni = 0; ni < 4; ni++) {
                int nr = nBase + ni * 8 + g;
                bfrag[ni][0] = __float_as_uint(Bs[nr * LD + kk + tig]);
                bfrag[ni][1] = __float_as_uint(Bs[nr * LD + kk + tig + 4]);
            }
            #pragma unroll
            for (int mi = 0; mi < 2; mi++)
                #pragma unroll
                for (int ni = 0; ni < 4; ni++) {
                    asm volatile(
                        "mma.sync.aligned.m16n8k8.row.col.f32.tf32.tf32.f32 "
                        "{%0,%1,%2,%3}, {%4,%5,%6,%7}, {%8,%9}, {%0,%1,%2,%3};\n"
                        : "+f"(acc[mi][ni][0]), "+f"(acc[mi][ni][1]),
                          "+f"(acc[mi][ni][2]), "+f"(acc[mi][ni][3])
                        : "r"(afrag[mi][0]), "r"(afrag[mi][1]),
                          "r"(afrag[mi][2]), "r"(afrag[mi][3]),
                          "r"(bfrag[ni][0]), "r"(bfrag[ni][1]));
                }
        }
        __syncthreads();
    }

    // epilogue: c0,c1 at (row g, cols 2t,2t+1); c2,c3 at (row g+8)
    #pragma unroll
    for (int mi = 0; mi < 2; mi++) {
        int r0 = bm + mBase + mi * 16 + g;
        #pragma unroll
        for (int ni = 0; ni < 4; ni++) {
            int col = bn + nBase + ni * 8 + 2 * tig;
            if (col >= N) continue;
            bool pair = (col + 1 < N);
            float bi0 = bias[col];
            float bi1 = pair ? bias[col + 1] : 0.0f;
            if (r0 < M) {
                float v0 = acc[mi][ni][0] + bi0;
                float v1 = acc[mi][ni][1] + bi1;
                if (do_relu) { v0 = fmaxf(v0, 0.0f); v1 = fmaxf(v1, 0.0f); }
                if (pair) *reinterpret_cast<float2*>(&C[(size_t)r0 * N + col]) = make_float2(v0, v1);
                else C[(size_t)r0 * N + col] = v0;
            }
            int r1 = r0 + 8;
            if (r1 < M) {
                float v2 = acc[mi][ni][2] + bi0;
                float v3 = acc[mi][ni][3] + bi1;
                if (do_relu) { v2 = fmaxf(v2, 0.0f); v3 = fmaxf(v3, 0.0f); }
                if (pair) *reinterpret_cast<float2*>(&C[(size_t)r1 * N + col]) = make_float2(v2, v3);
                else C[(size_t)r1 * N + col] = v2;
            }
        }
    }
}

// ---------------- launch ----------------

static inline dim3 gemm_grid_f32(int M, int N) {
    return dim3((N + 63) / 64, (M + 63) / 64);
}
static inline dim3 gemm_grid_tf32(int M, int N) {
    return dim3((N + 63) / 64, (M + 127) / 128);
}

extern "C" void kernel_launch(void* const* d_in, const int* in_sizes, int n_in,
                              void* d_out, int out_size) {
    const float* category  = (const float*)d_in[0];
    const float* sub_cat   = (const float*)d_in[1];
    const float* element   = (const float*)d_in[2];
    const float* brand     = (const float*)d_in[3];
    const float* price     = (const float*)d_in[4];
    const int*   edge_idx  = (const int*)d_in[5];
    const int*   batch     = (const int*)d_in[6];
    const float* W_init = (const float*)d_in[7];
    const float* b_init = (const float*)d_in[8];
    const float* W_msg  = (const float*)d_in[9];
    const float* b_msg  = (const float*)d_in[10];
    const float* W_ih   = (const float*)d_in[11];
    const float* W_hh   = (const float*)d_in[12];
    const float* b_ih   = (const float*)d_in[13];
    const float* b_hh   = (const float*)d_in[14];
    const float* W_last = (const float*)d_in[15];
    const float* b_last = (const float*)d_in[16];
    const float* W_g1   = (const float*)d_in[17];
    const float* b_g1   = (const float*)d_in[18];
    const float* W_g2   = (const float*)d_in[19];
    const float* b_g2   = (const float*)d_in[20];
    const float* W_fc   = (const float*)d_in[21];
    const float* b_fc   = (const float*)d_in[22];
    float* out = (float*)d_out;

    float *feat, *proj, *h, *m, *gi, *gh, *featlast, *last, *pooled;
    cudaGetSymbolAddress((void**)&feat, g_feat);
    cudaGetSymbolAddress((void**)&proj, g_proj);
    cudaGetSymbolAddress((void**)&h, g_h);
    cudaGetSymbolAddress((void**)&m, g_m);
    cudaGetSymbolAddress((void**)&gi, g_gi);
    cudaGetSymbolAddress((void**)&gh, g_gh);
    cudaGetSymbolAddress((void**)&featlast, g_featlast);
    cudaGetSymbolAddress((void**)&last, g_last);
    cudaGetSymbolAddress((void**)&pooled, g_pooled);

    const size_t NF = (size_t)N_NODES * IN_DIM;
    const size_t NH = (size_t)N_NODES * HID;

    // 1) feat concat
    concat_feat_kernel<<<(unsigned)((NF + 255) / 256), 256>>>(category, sub_cat, element, brand, price);

    // 2) proj = feat @ W_init^T + b_init   [81920,128]  (TF32 tensor)
    tgemm_nt_kernel<<<gemm_grid_tf32(N_NODES, INIT_DIM), 256>>>(feat, W_init, b_init, proj, N_NODES, INIT_DIM, IN_DIM, 0);

    // 3) h = proj @ W_msg^T + b_msg        [81920,100]  (fp32, short error chain)
    sgemm_nt_kernel<<<gemm_grid_f32(N_NODES, HID), 256>>>(proj, W_msg, b_msg, h, N_NODES, HID, INIT_DIM, 0);

    // 4) message passing mean
    zero_msum_cnt_kernel<<<(unsigned)((NH + 255) / 256), 256>>>();
    edge_scatter_kernel<<<(N_EDGES + 1) / 2, 256>>>(edge_idx);
    mean_kernel<<<(unsigned)((NH + 255) / 256), 256>>>();

    // 5) GRU (TF32 tensor)
    tgemm_nt_kernel<<<gemm_grid_tf32(N_NODES, 3 * HID), 256>>>(m, W_ih, b_ih, gi, N_NODES, 3 * HID, HID, 0);
    tgemm_nt_kernel<<<gemm_grid_tf32(N_NODES, 3 * HID), 256>>>(h, W_hh, b_hh, gh, N_NODES, 3 * HID, HID, 0);
    gru_kernel<<<(unsigned)((NH + 255) / 256), 256>>>();

    // 6) last-node projection, broadcast add (fp32, tiny)
    gather_last_kernel<<<(unsigned)(((size_t)N_SESS * IN_DIM + 255) / 256), 256>>>();
    sgemm_nt_kernel<<<gemm_grid_f32(N_SESS, HID), 256>>>(featlast, W_last, b_last, last, N_SESS, HID, IN_DIM, 0);
    add_last_kernel<<<(unsigned)((NH + 255) / 256), 256>>>(batch);

    // 7) attention gate: tmp = relu(h@Wg1^T + bg1) (TF32); gate = tmp.Wg2 + bg2
    tgemm_nt_kernel<<<gemm_grid_tf32(N_NODES, HID), 256>>>(h, W_g1, b_g1, gi, N_NODES, HID, HID, 1);
    gate_dot_kernel<<<(N_NODES * 32 + 255) / 256, 256>>>(W_g2, b_g2);

    // 8) per-session softmax + pooling
    pool_kernel<<<N_SESS, 128>>>();

    // 9) out = pooled @ W_fc^T + b_fc   [4096, 50000]  (TF32 tensor)
    tgemm_nt_kernel<<<gemm_grid_tf32(N_SESS, N_ITEMS), 256>>>(pooled, W_fc, b_fc, out, N_SESS, N_ITEMS, HID, 0);
}